// round 2
// baseline (speedup 1.0000x reference)
#include <cuda_runtime.h>
#include <math.h>

#define NP 16384
#define MAXK 64
#define RAD2 0.00390625f   /* (1/16)^2 */

// ---------------- scratch (no allocations allowed) ----------------
__device__ int   g_bstride;          // 1 if batch stored as int32, 2 if int64
__device__ int   g_start[8];
__device__ int   g_end[8];
__device__ int   g_nidx[NP * MAXK];
__device__ float g_nd2 [NP * MAXK];
__device__ int   g_cnt [NP];
__device__ float g_f1  [NP * 8];
__device__ float g_f2  [NP * 16];

// ---------------- detect batch word stride ----------------
// batch is sorted non-decreasing. If stored as int64, reading as int32 gives
// (value, 0, value, 0, ...) which has a decrease in the trailing words
// (last cloud value >= 1). If int32, the trailing 64 words are all equal.
__global__ void detect_kernel(const int* __restrict__ bw) {
    if (threadIdx.x == 0 && blockIdx.x == 0) {
        int stride = 1;
        for (int k = NP - 64; k < NP - 1; ++k) {
            if (bw[k] > bw[k + 1]) { stride = 2; break; }
        }
        g_bstride = stride;
    }
}

// ---------------- per-cloud [start, end) ranges ----------------
__global__ void bounds_kernel(const int* __restrict__ bw) {
    int i = blockIdx.x * blockDim.x + threadIdx.x;
    if (i >= NP) return;
    int s = g_bstride;
    int b = bw[i * s];
    if (i == 0      || bw[(i - 1) * s] != b) g_start[b] = i;
    if (i == NP - 1 || bw[(i + 1) * s] != b) g_end[b]   = i + 1;
}

// ---------------- radius-graph construction ----------------
// One thread per point; smem-tiled scan of the (<=2) clouds spanned by the block.
// Keeps the 64 smallest-d2 neighbors (ties -> lower index), matching lax.top_k.
__global__ void nbr_kernel(const float* __restrict__ pos, const int* __restrict__ bw) {
    const int TB = 128;
    __shared__ float sx[TB], sy[TB], sz[TB];
    int i = blockIdx.x * TB + threadIdx.x;
    int s = g_bstride;
    int b  = bw[i * s];
    int cs = g_start[b], ce = g_end[b];
    int bA = bw[(blockIdx.x * TB) * s];
    int bB = bw[(blockIdx.x * TB + TB - 1) * s];
    int jmin = g_start[bA], jmax = g_end[bB];

    float px = pos[3 * i], py = pos[3 * i + 1], pz = pos[3 * i + 2];
    int cnt = 0;
    const int base = i * MAXK;

    for (int jb = jmin; jb < jmax; jb += TB) {
        int jl = jb + threadIdx.x;
        if (jl < jmax) {
            sx[threadIdx.x] = pos[3 * jl];
            sy[threadIdx.x] = pos[3 * jl + 1];
            sz[threadIdx.x] = pos[3 * jl + 2];
        }
        __syncthreads();
        int lo = jb > cs ? jb : cs;
        int hi = jb + TB < ce ? jb + TB : ce;
        for (int j = lo; j < hi; ++j) {
            int t = j - jb;
            float dx = sx[t] - px, dy = sy[t] - py, dz = sz[t] - pz;
            float d2 = fmaf(dx, dx, fmaf(dy, dy, dz * dz));
            if (d2 <= RAD2) {
                if (cnt < MAXK) {
                    g_nidx[base + cnt] = j;
                    g_nd2 [base + cnt] = d2;
                    ++cnt;
                } else {
                    // Exact top-64 fallback (statistically never taken for this data).
                    float mx = g_nd2[base]; int mp = 0;
                    for (int q = 1; q < MAXK; ++q) {
                        float v = g_nd2[base + q];
                        if (v > mx || (v == mx && g_nidx[base + q] > g_nidx[base + mp])) {
                            mx = v; mp = q;
                        }
                    }
                    if (d2 < mx) { g_nd2[base + mp] = d2; g_nidx[base + mp] = j; }
                }
            }
        }
        __syncthreads();
    }
    g_cnt[i] = cnt;
}

// ---------------- PointNetConv layer ----------------
// msg = relu([x_j, pos_j - pos_i] @ W1 + b1); max-agg over neighbors;
// out = celu(agg @ W2 + b2). relu>=0 and self-loop guaranteed -> agg init 0 is exact.
template <int CIN, int CMID, int COUT>
__global__ void conv_kernel(const float* __restrict__ x_ext, int xsel,
                            const float* __restrict__ pos,
                            const float* __restrict__ W1, const float* __restrict__ b1,
                            const float* __restrict__ W2, const float* __restrict__ b2,
                            float* __restrict__ out_ext, int osel) {
    constexpr int CF = CIN + 3;
    __shared__ float sW1[CF * CMID];
    __shared__ float sb1[CMID];
    __shared__ float sW2[CMID * COUT];
    __shared__ float sb2[COUT];
    for (int t = threadIdx.x; t < CF * CMID;   t += blockDim.x) sW1[t] = W1[t];
    for (int t = threadIdx.x; t < CMID;        t += blockDim.x) sb1[t] = b1[t];
    for (int t = threadIdx.x; t < CMID * COUT; t += blockDim.x) sW2[t] = W2[t];
    for (int t = threadIdx.x; t < COUT;        t += blockDim.x) sb2[t] = b2[t];
    __syncthreads();

    const float* x  = (xsel == 0) ? x_ext  : (xsel == 1) ? g_f1 : g_f2;
    float*       ob = (osel == 0) ? out_ext : (osel == 1) ? g_f1 : g_f2;

    int i = blockIdx.x * blockDim.x + threadIdx.x;
    float px = pos[3 * i], py = pos[3 * i + 1], pz = pos[3 * i + 2];

    float agg[CMID];
#pragma unroll
    for (int m = 0; m < CMID; ++m) agg[m] = 0.0f;

    int cnt  = g_cnt[i];
    int base = i * MAXK;
    for (int n = 0; n < cnt; ++n) {
        int j = g_nidx[base + n];
        float feat[CF];
#pragma unroll
        for (int c = 0; c < CIN; ++c) feat[c] = x[j * CIN + c];
        feat[CIN]     = pos[3 * j]     - px;
        feat[CIN + 1] = pos[3 * j + 1] - py;
        feat[CIN + 2] = pos[3 * j + 2] - pz;
#pragma unroll
        for (int m = 0; m < CMID; ++m) {
            float h = sb1[m];
#pragma unroll
            for (int f = 0; f < CF; ++f) h = fmaf(feat[f], sW1[f * CMID + m], h);
            h = h > 0.0f ? h : 0.0f;
            agg[m] = fmaxf(agg[m], h);
        }
    }
#pragma unroll
    for (int o = 0; o < COUT; ++o) {
        float acc = sb2[o];
#pragma unroll
        for (int m = 0; m < CMID; ++m) acc = fmaf(agg[m], sW2[m * COUT + o], acc);
        ob[i * COUT + o] = acc > 0.0f ? acc : expm1f(acc);   // celu(alpha=1)
    }
}

// ---------------- tuple epilogue: pos (and batch) copies ----------------
__global__ void epi_kernel(const float* __restrict__ pos, const int* __restrict__ bw,
                           float* __restrict__ out, int write_batch) {
    int i = blockIdx.x * blockDim.x + threadIdx.x;
    if (i < NP * 3) out[i] = pos[i];
    if (write_batch && i < NP) {
        out[NP * 3 + NP * 32 + i] = (float)bw[i * g_bstride];
    }
}

extern "C" void kernel_launch(void* const* d_in, const int* in_sizes, int n_in,
                              void* d_out, int out_size) {
    const float* pos = (const float*)d_in[0];
    /* d_in[1] = rgb, unused by the reference */
    const int*   bw  = (const int*)d_in[2];
    const float* W1a = (const float*)d_in[3];
    const float* b1a = (const float*)d_in[4];
    const float* W2a = (const float*)d_in[5];
    const float* b2a = (const float*)d_in[6];
    const float* W1b = (const float*)d_in[7];
    const float* b1b = (const float*)d_in[8];
    const float* W2b = (const float*)d_in[9];
    const float* b2b = (const float*)d_in[10];
    const float* W1c = (const float*)d_in[11];
    const float* b1c = (const float*)d_in[12];
    const float* W2c = (const float*)d_in[13];
    const float* b2c = (const float*)d_in[14];

    float* fout = (float*)d_out;
    float* conv_out;
    int write_pos = 0, write_batch = 0;
    const int POSN = NP * 3;                 // 49152
    if (out_size >= POSN + NP * 32 + NP) {   // (pos, out, batch) as float32
        conv_out = fout + POSN; write_pos = 1; write_batch = 1;
    } else if (out_size >= POSN + NP * 32) { // (pos, out)
        conv_out = fout + POSN; write_pos = 1;
    } else {                                 // out only
        conv_out = fout;
    }

    detect_kernel<<<1, 32>>>(bw);
    bounds_kernel<<<NP / 256, 256>>>(bw);
    nbr_kernel<<<NP / 128, 128>>>(pos, bw);

    conv_kernel<3, 8, 8>  <<<NP / 128, 128>>>(pos, 0, pos, W1a, b1a, W2a, b2a, nullptr, 1);
    conv_kernel<8, 16, 16><<<NP / 128, 128>>>(nullptr, 1, pos, W1b, b1b, W2b, b2b, nullptr, 2);
    conv_kernel<16, 32, 32><<<NP / 128, 128>>>(nullptr, 2, pos, W1c, b1c, W2c, b2c, conv_out, 0);

    if (write_pos) {
        epi_kernel<<<(NP * 3 + 255) / 256, 256>>>(pos, bw, fout, write_batch);
    }
}

// round 3
// speedup vs baseline: 2.1002x; 2.1002x over previous
#include <cuda_runtime.h>
#include <math.h>

#define NP   16384
#define MAXK 64
#define RAD2 0.00390625f   /* (1/16)^2 */
#define GRID 16
#define TOTC 32768         /* 8 clouds * 16^3 cells */

// ---------------- scratch (no allocations allowed) ----------------
__device__ int   g_bstride;            // 1 if batch int32, 2 if int64
__device__ int   g_pcell[NP];
__device__ int   g_cellcnt[TOTC];
__device__ int   g_cellstart[TOTC + 1];
__device__ int   g_cellptr[TOTC];
__device__ int   g_sorted[NP];
__device__ int   g_nidx[NP * MAXK];
__device__ float g_nrel[NP * MAXK * 3];
__device__ int   g_cnt[NP];
__device__ float g_f1[NP * 8];
__device__ float g_f2[NP * 16];

// ---------------- zero cell counts + detect batch word stride ----------------
__global__ void zero_detect_kernel(const int* __restrict__ bw) {
    int i = blockIdx.x * blockDim.x + threadIdx.x;
    if (i < TOTC) g_cellcnt[i] = 0;
    if (i == 0) {
        // batch sorted non-decreasing; int64 read as int32 interleaves zeros.
        int stride = 1;
        for (int k = NP - 64; k < NP - 1; ++k)
            if (bw[k] > bw[k + 1]) { stride = 2; break; }
        g_bstride = stride;
    }
}

// ---------------- bin points into (cloud, cz, cy, cx) cells ----------------
__device__ __forceinline__ int clamp16(int v) { return v < 0 ? 0 : (v > 15 ? 15 : v); }

__global__ void count_kernel(const float* __restrict__ pos, const int* __restrict__ bw) {
    int i = blockIdx.x * blockDim.x + threadIdx.x;
    int b  = bw[i * g_bstride];
    int cx = clamp16((int)(pos[3 * i]     * 16.0f));
    int cy = clamp16((int)(pos[3 * i + 1] * 16.0f));
    int cz = clamp16((int)(pos[3 * i + 2] * 16.0f));
    int c  = (b << 12) | (cz << 8) | (cy << 4) | cx;
    g_pcell[i] = c;
    atomicAdd(&g_cellcnt[c], 1);
}

// ---------------- exclusive scan of 32768 cell counts (1 block) ----------------
__global__ void scan_kernel() {
    __shared__ int swarp[32];
    int t = threadIdx.x;                 // 1024 threads, 32 cells each
    int base = t * 32;
    int vals[32];
    int run = 0;
#pragma unroll
    for (int q = 0; q < 32; ++q) { vals[q] = run; run += g_cellcnt[base + q]; }

    int lane = t & 31, wid = t >> 5;
    int x = run;                         // warp inclusive scan of per-thread totals
#pragma unroll
    for (int ofs = 1; ofs < 32; ofs <<= 1) {
        int y = __shfl_up_sync(0xffffffffu, x, ofs);
        if (lane >= ofs) x += y;
    }
    if (lane == 31) swarp[wid] = x;
    __syncthreads();
    if (wid == 0) {
        int z = swarp[lane];
#pragma unroll
        for (int ofs = 1; ofs < 32; ofs <<= 1) {
            int y = __shfl_up_sync(0xffffffffu, z, ofs);
            if (lane >= ofs) z += y;
        }
        swarp[lane] = z;
    }
    __syncthreads();
    int excl = (wid > 0 ? swarp[wid - 1] : 0) + (x - run);
#pragma unroll
    for (int q = 0; q < 32; ++q) {
        int s = excl + vals[q];
        g_cellstart[base + q] = s;
        g_cellptr[base + q]   = s;
    }
    if (t == 1023) g_cellstart[TOTC] = NP;
}

__global__ void scatter_kernel() {
    int i = blockIdx.x * blockDim.x + threadIdx.x;
    int c = g_pcell[i];
    int dst = atomicAdd(&g_cellptr[c], 1);
    g_sorted[dst] = i;
}

// ---------------- radius neighbors via grid (9 contiguous x-ranges) ----------------
__global__ void nbr_kernel(const float* __restrict__ pos) {
    int i = blockIdx.x * blockDim.x + threadIdx.x;
    int c0 = g_pcell[i];
    int cx = c0 & 15, cy = (c0 >> 4) & 15, cz = (c0 >> 8) & 15, b = c0 >> 12;
    float px = pos[3 * i], py = pos[3 * i + 1], pz = pos[3 * i + 2];
    int cnt = 0;
    const int base = i * MAXK;
    int zlo = cz > 0 ? cz - 1 : 0, zhi = cz < 15 ? cz + 1 : 15;
    int ylo = cy > 0 ? cy - 1 : 0, yhi = cy < 15 ? cy + 1 : 15;
    int xlo = cx > 0 ? cx - 1 : 0, xhi = cx < 15 ? cx + 1 : 15;

    for (int zz = zlo; zz <= zhi; ++zz) {
        for (int yy = ylo; yy <= yhi; ++yy) {
            int crow = (b << 12) | (zz << 8) | (yy << 4);
            int s = g_cellstart[crow + xlo];
            int e = g_cellstart[crow + xhi + 1];
            for (int p = s; p < e; ++p) {
                int j = g_sorted[p];
                float dx = pos[3 * j]     - px;
                float dy = pos[3 * j + 1] - py;
                float dz = pos[3 * j + 2] - pz;
                float d2 = fmaf(dx, dx, fmaf(dy, dy, dz * dz));
                if (d2 <= RAD2) {
                    if (cnt < MAXK) {
                        g_nidx[base + cnt] = j;
                        g_nrel[(base + cnt) * 3 + 0] = dx;
                        g_nrel[(base + cnt) * 3 + 1] = dy;
                        g_nrel[(base + cnt) * 3 + 2] = dz;
                        ++cnt;
                    } else {
                        // Exact smallest-64 eviction (statistically never taken).
                        float mx = -1.0f; int mp = 0;
                        for (int q = 0; q < MAXK; ++q) {
                            float rx = g_nrel[(base + q) * 3];
                            float ry = g_nrel[(base + q) * 3 + 1];
                            float rz = g_nrel[(base + q) * 3 + 2];
                            float v = fmaf(rx, rx, fmaf(ry, ry, rz * rz));
                            if (v > mx) { mx = v; mp = q; }
                        }
                        if (d2 < mx) {
                            g_nidx[base + mp] = j;
                            g_nrel[(base + mp) * 3 + 0] = dx;
                            g_nrel[(base + mp) * 3 + 1] = dy;
                            g_nrel[(base + mp) * 3 + 2] = dz;
                        }
                    }
                }
            }
        }
    }
    g_cnt[i] = cnt;
}

// ---------------- PointNetConv: 8 lanes per point ----------------
// msg = relu([x_j, rel] @ W1 + b1), max-agg (init 0 exact: relu>=0, self-loop),
// out = celu(agg @ W2 + b2).
template <int CIN, int CMID, int COUT>
__global__ void conv_kernel(const float* __restrict__ x_ext, int xsel,
                            const float* __restrict__ W1, const float* __restrict__ b1,
                            const float* __restrict__ W2, const float* __restrict__ b2,
                            float* __restrict__ out_ext, int osel) {
    constexpr int CF  = CIN + 3;
    constexpr int SUB = 8;
    constexpr int PPB = 128 / SUB;   // 16 points per block
    constexpr int OPT = COUT / SUB;

    __shared__ float sW1[CF * CMID];
    __shared__ float sb1[CMID];
    __shared__ float sW2[CMID * COUT];
    __shared__ float sb2[COUT];
    for (int t = threadIdx.x; t < CF * CMID;   t += blockDim.x) sW1[t] = W1[t];
    for (int t = threadIdx.x; t < CMID;        t += blockDim.x) sb1[t] = b1[t];
    for (int t = threadIdx.x; t < CMID * COUT; t += blockDim.x) sW2[t] = W2[t];
    for (int t = threadIdx.x; t < COUT;        t += blockDim.x) sb2[t] = b2[t];
    __syncthreads();

    const float* x  = (xsel == 0) ? x_ext  : (xsel == 1) ? g_f1 : g_f2;
    float*       ob = (osel == 0) ? out_ext : (osel == 1) ? g_f1 : g_f2;

    int lp = threadIdx.x >> 3;
    int t  = threadIdx.x & 7;
    int i  = blockIdx.x * PPB + lp;

    float agg[CMID];
#pragma unroll
    for (int m = 0; m < CMID; ++m) agg[m] = 0.0f;

    int cnt  = g_cnt[i];
    int base = i * MAXK;
    for (int n = t; n < cnt; n += SUB) {
        int j = g_nidx[base + n];
        float feat[CF];
#pragma unroll
        for (int c = 0; c < CIN; ++c) feat[c] = x[j * CIN + c];
        feat[CIN]     = g_nrel[(base + n) * 3 + 0];
        feat[CIN + 1] = g_nrel[(base + n) * 3 + 1];
        feat[CIN + 2] = g_nrel[(base + n) * 3 + 2];
#pragma unroll
        for (int m = 0; m < CMID; ++m) {
            float h = sb1[m];
#pragma unroll
            for (int f = 0; f < CF; ++f) h = fmaf(feat[f], sW1[f * CMID + m], h);
            h = h > 0.0f ? h : 0.0f;
            agg[m] = fmaxf(agg[m], h);
        }
    }
    // butterfly max across the 8 lanes of this point
#pragma unroll
    for (int ofs = 1; ofs < SUB; ofs <<= 1) {
#pragma unroll
        for (int m = 0; m < CMID; ++m)
            agg[m] = fmaxf(agg[m], __shfl_xor_sync(0xffffffffu, agg[m], ofs));
    }
    // each lane computes COUT/8 outputs
#pragma unroll
    for (int q = 0; q < OPT; ++q) {
        int o = t * OPT + q;
        float acc = sb2[o];
#pragma unroll
        for (int m = 0; m < CMID; ++m) acc = fmaf(agg[m], sW2[m * COUT + o], acc);
        ob[i * COUT + o] = acc > 0.0f ? acc : expm1f(acc);   // celu(alpha=1)
    }
}

// ---------------- tuple epilogue: pos (and batch) copies ----------------
__global__ void epi_kernel(const float* __restrict__ pos, const int* __restrict__ bw,
                           float* __restrict__ out, int write_batch) {
    int i = blockIdx.x * blockDim.x + threadIdx.x;
    if (i < NP * 3) out[i] = pos[i];
    if (write_batch && i < NP) {
        out[NP * 3 + NP * 32 + i] = (float)bw[i * g_bstride];
    }
}

extern "C" void kernel_launch(void* const* d_in, const int* in_sizes, int n_in,
                              void* d_out, int out_size) {
    const float* pos = (const float*)d_in[0];
    /* d_in[1] = rgb, unused by the reference */
    const int*   bw  = (const int*)d_in[2];
    const float* W1a = (const float*)d_in[3];
    const float* b1a = (const float*)d_in[4];
    const float* W2a = (const float*)d_in[5];
    const float* b2a = (const float*)d_in[6];
    const float* W1b = (const float*)d_in[7];
    const float* b1b = (const float*)d_in[8];
    const float* W2b = (const float*)d_in[9];
    const float* b2b = (const float*)d_in[10];
    const float* W1c = (const float*)d_in[11];
    const float* b1c = (const float*)d_in[12];
    const float* W2c = (const float*)d_in[13];
    const float* b2c = (const float*)d_in[14];

    float* fout = (float*)d_out;
    float* conv_out;
    int write_pos = 0, write_batch = 0;
    const int POSN = NP * 3;                 // 49152
    if (out_size >= POSN + NP * 32 + NP) {   // (pos, out, batch) as float32
        conv_out = fout + POSN; write_pos = 1; write_batch = 1;
    } else if (out_size >= POSN + NP * 32) { // (pos, out)
        conv_out = fout + POSN; write_pos = 1;
    } else {                                 // out only
        conv_out = fout;
    }

    zero_detect_kernel<<<TOTC / 256, 256>>>(bw);
    count_kernel<<<NP / 256, 256>>>(pos, bw);
    scan_kernel<<<1, 1024>>>();
    scatter_kernel<<<NP / 256, 256>>>();
    nbr_kernel<<<NP / 128, 128>>>(pos);

    conv_kernel<3, 8, 8>   <<<NP / 16, 128>>>(pos, 0, W1a, b1a, W2a, b2a, nullptr, 1);
    conv_kernel<8, 16, 16> <<<NP / 16, 128>>>(nullptr, 1, W1b, b1b, W2b, b2b, nullptr, 2);
    conv_kernel<16, 32, 32><<<NP / 16, 128>>>(nullptr, 2, W1c, b1c, W2c, b2c, conv_out, 0);

    if (write_pos) {
        epi_kernel<<<(NP * 3 + 255) / 256, 256>>>(pos, bw, fout, write_batch);
    }
}